// round 9
// baseline (speedup 1.0000x reference)
#include <cuda_runtime.h>
#include <math.h>

#define B_    4
#define L_    2048
#define E_    1024
#define H_    16
#define D_    64
#define MTOT  (B_ * L_)   // 8192

// ---------------- scratch (device globals: no allocations allowed) ----------------
__device__ float g_q[MTOT * E_];
__device__ float g_k[MTOT * E_];
__device__ float g_v[MTOT * E_];
__device__ float g_attn[MTOT * E_];

// =================================================================================
// Projection GEMM:  Y[M,N] = X[M,K] @ W[N,K]^T + bias[N]
// Both operands are K-contiguous (NT GEMM). 128x128 tile, BK=16, 256 threads,
// 8x8 micro-tile per thread, smem staged transposed ([k][m]) for float4 reads.
// =================================================================================
#define GT_M   128
#define GT_N   128
#define GT_K   16
#define GT_PAD 4     // pad 4 keeps 16B alignment for float4 reads, 2-way store conflict max

__global__ __launch_bounds__(256, 2)
void gemm_nt_bias(const float* __restrict__ X, const float* __restrict__ W,
                  const float* __restrict__ bias, float* __restrict__ Y,
                  int M, int N, int K)
{
    __shared__ float Xs[GT_K][GT_M + GT_PAD];
    __shared__ float Ws[GT_K][GT_N + GT_PAD];

    const int tid  = threadIdx.x;
    const int tx   = tid & 15;
    const int ty   = tid >> 4;
    const int m0   = blockIdx.y * GT_M;
    const int n0   = blockIdx.x * GT_N;
    const int lrow = tid >> 2;        // 0..63
    const int lk   = (tid & 3) << 2;  // 0,4,8,12

    float acc[8][8];
    #pragma unroll
    for (int i = 0; i < 8; i++)
        #pragma unroll
        for (int j = 0; j < 8; j++) acc[i][j] = 0.0f;

    for (int k0 = 0; k0 < K; k0 += GT_K) {
        #pragma unroll
        for (int half = 0; half < 2; half++) {
            int r = lrow + half * 64;
            float4 xv = *(const float4*)&X[(size_t)(m0 + r) * K + k0 + lk];
            Xs[lk + 0][r] = xv.x; Xs[lk + 1][r] = xv.y;
            Xs[lk + 2][r] = xv.z; Xs[lk + 3][r] = xv.w;
            float4 wv = *(const float4*)&W[(size_t)(n0 + r) * K + k0 + lk];
            Ws[lk + 0][r] = wv.x; Ws[lk + 1][r] = wv.y;
            Ws[lk + 2][r] = wv.z; Ws[lk + 3][r] = wv.w;
        }
        __syncthreads();

        #pragma unroll
        for (int kk = 0; kk < GT_K; kk++) {
            float a[8], b[8];
            *(float4*)&a[0] = *(const float4*)&Xs[kk][ty * 4];
            *(float4*)&a[4] = *(const float4*)&Xs[kk][64 + ty * 4];
            *(float4*)&b[0] = *(const float4*)&Ws[kk][tx * 4];
            *(float4*)&b[4] = *(const float4*)&Ws[kk][64 + tx * 4];
            #pragma unroll
            for (int i = 0; i < 8; i++)
                #pragma unroll
                for (int j = 0; j < 8; j++)
                    acc[i][j] = fmaf(a[i], b[j], acc[i][j]);
        }
        __syncthreads();
    }

    // epilogue: add bias, float4 stores
    #pragma unroll
    for (int i = 0; i < 8; i++) {
        int m = m0 + ((i < 4) ? (ty * 4 + i) : (64 + ty * 4 + (i - 4)));
        #pragma unroll
        for (int jh = 0; jh < 2; jh++) {
            int n = n0 + jh * 64 + tx * 4;
            float4 o;
            o.x = acc[i][jh * 4 + 0] + bias[n + 0];
            o.y = acc[i][jh * 4 + 1] + bias[n + 1];
            o.z = acc[i][jh * 4 + 2] + bias[n + 2];
            o.w = acc[i][jh * 4 + 3] + bias[n + 3];
            *(float4*)&Y[(size_t)m * N + n] = o;
        }
    }
}

// =================================================================================
// Flash attention (fp32, online softmax). One block per (b,h, 64-row q tile).
// 256 threads as 16x16; each thread owns a 4x4 micro-tile of S (64x64) and of
// O (64 rows x 64 dims). Row-group = 16 lanes sharing ty -> shfl_xor reductions.
// Smem rows padded to 65 floats: compute-phase scalar reads are conflict-free.
// =================================================================================
#define FA_BM  64
#define FA_BN  64
#define FA_LDS 65

__global__ __launch_bounds__(256, 2)
void flash_attn(const float* __restrict__ Q, const float* __restrict__ K,
                const float* __restrict__ V, float* __restrict__ O)
{
    extern __shared__ float sm[];
    float* Qs = sm;                   // [64][65]
    float* Ks = Qs + 64 * FA_LDS;     // [64][65]
    float* Vs = Ks + 64 * FA_LDS;     // [64][65]
    float* Ps = Vs + 64 * FA_LDS;     // [64][65]

    const int tid = threadIdx.x;
    const int tx  = tid & 15;
    const int ty  = tid >> 4;
    const int bh  = blockIdx.y;
    const int b   = bh >> 4;          // / H_
    const int h   = bh & 15;          // % H_
    const int q0  = blockIdx.x * FA_BM;

    const float* qg = Q + ((size_t)b * L_ + q0) * E_ + h * D_;
    const float* kg = K + ((size_t)b * L_) * E_ + h * D_;
    const float* vg = V + ((size_t)b * L_) * E_ + h * D_;

    const float scale = 0.03125f;     // 1/sqrt(1024)

    // load + scale Q tile (64 rows x 64 dims)
    #pragma unroll
    for (int p = 0; p < 4; p++) {
        int idx = p * 256 + tid;
        int r   = idx >> 4;
        int dc  = (idx & 15) << 2;
        float4 v = *(const float4*)&qg[(size_t)r * E_ + dc];
        Qs[r * FA_LDS + dc + 0] = v.x * scale;
        Qs[r * FA_LDS + dc + 1] = v.y * scale;
        Qs[r * FA_LDS + dc + 2] = v.z * scale;
        Qs[r * FA_LDS + dc + 3] = v.w * scale;
    }

    float m_i[4], l_i[4], acc[4][4];
    #pragma unroll
    for (int i = 0; i < 4; i++) {
        m_i[i] = -INFINITY;
        l_i[i] = 0.0f;
        #pragma unroll
        for (int j = 0; j < 4; j++) acc[i][j] = 0.0f;
    }

    for (int n0 = 0; n0 < L_; n0 += FA_BN) {
        __syncthreads();   // prev tile fully consumed (and Q visible on first iter)

        // load K, V tiles (natural layout, padded rows)
        #pragma unroll
        for (int p = 0; p < 4; p++) {
            int idx = p * 256 + tid;
            int r   = idx >> 4;
            int dc  = (idx & 15) << 2;
            float4 kv = *(const float4*)&kg[(size_t)(n0 + r) * E_ + dc];
            Ks[r * FA_LDS + dc + 0] = kv.x;
            Ks[r * FA_LDS + dc + 1] = kv.y;
            Ks[r * FA_LDS + dc + 2] = kv.z;
            Ks[r * FA_LDS + dc + 3] = kv.w;
            float4 vv = *(const float4*)&vg[(size_t)(n0 + r) * E_ + dc];
            Vs[r * FA_LDS + dc + 0] = vv.x;
            Vs[r * FA_LDS + dc + 1] = vv.y;
            Vs[r * FA_LDS + dc + 2] = vv.z;
            Vs[r * FA_LDS + dc + 3] = vv.w;
        }
        __syncthreads();

        // ---- GEMM1: s[4][4] = (Q tile) @ (K tile)^T, inner product along d ----
        float s[4][4];
        #pragma unroll
        for (int i = 0; i < 4; i++)
            #pragma unroll
            for (int j = 0; j < 4; j++) s[i][j] = 0.0f;

        #pragma unroll 8
        for (int kk = 0; kk < D_; kk++) {
            float a[4], bb[4];
            #pragma unroll
            for (int i = 0; i < 4; i++) a[i]  = Qs[(ty * 4 + i) * FA_LDS + kk];
            #pragma unroll
            for (int j = 0; j < 4; j++) bb[j] = Ks[(tx * 4 + j) * FA_LDS + kk];
            #pragma unroll
            for (int i = 0; i < 4; i++)
                #pragma unroll
                for (int j = 0; j < 4; j++)
                    s[i][j] = fmaf(a[i], bb[j], s[i][j]);
        }

        // ---- online softmax (row group = 16 lanes, shfl_xor over tx bits) ----
        #pragma unroll
        for (int i = 0; i < 4; i++) {
            float rmax = fmaxf(fmaxf(s[i][0], s[i][1]), fmaxf(s[i][2], s[i][3]));
            rmax = fmaxf(rmax, __shfl_xor_sync(0xffffffffu, rmax, 1));
            rmax = fmaxf(rmax, __shfl_xor_sync(0xffffffffu, rmax, 2));
            rmax = fmaxf(rmax, __shfl_xor_sync(0xffffffffu, rmax, 4));
            rmax = fmaxf(rmax, __shfl_xor_sync(0xffffffffu, rmax, 8));
            float mnew = fmaxf(m_i[i], rmax);

            float p0 = __expf(s[i][0] - mnew);
            float p1 = __expf(s[i][1] - mnew);
            float p2 = __expf(s[i][2] - mnew);
            float p3 = __expf(s[i][3] - mnew);
            float rsum = (p0 + p1) + (p2 + p3);
            rsum += __shfl_xor_sync(0xffffffffu, rsum, 1);
            rsum += __shfl_xor_sync(0xffffffffu, rsum, 2);
            rsum += __shfl_xor_sync(0xffffffffu, rsum, 4);
            rsum += __shfl_xor_sync(0xffffffffu, rsum, 8);

            float alpha = __expf(m_i[i] - mnew);   // 0 when m_i = -inf
            l_i[i] = l_i[i] * alpha + rsum;
            m_i[i] = mnew;
            #pragma unroll
            for (int j = 0; j < 4; j++) acc[i][j] *= alpha;

            int prow = (ty * 4 + i) * FA_LDS + tx * 4;
            Ps[prow + 0] = p0; Ps[prow + 1] = p1;
            Ps[prow + 2] = p2; Ps[prow + 3] = p3;
        }
        __syncthreads();

        // ---- GEMM2: acc += P @ V ----
        #pragma unroll 8
        for (int nn = 0; nn < FA_BN; nn++) {
            float a[4], bb[4];
            #pragma unroll
            for (int i = 0; i < 4; i++) a[i]  = Ps[(ty * 4 + i) * FA_LDS + nn];
            #pragma unroll
            for (int j = 0; j < 4; j++) bb[j] = Vs[nn * FA_LDS + tx * 4 + j];
            #pragma unroll
            for (int i = 0; i < 4; i++)
                #pragma unroll
                for (int j = 0; j < 4; j++)
                    acc[i][j] = fmaf(a[i], bb[j], acc[i][j]);
        }
    }

    // epilogue: normalize, write [b, q, h, d]
    #pragma unroll
    for (int i = 0; i < 4; i++) {
        float inv = 1.0f / l_i[i];
        float4 o;
        o.x = acc[i][0] * inv;
        o.y = acc[i][1] * inv;
        o.z = acc[i][2] * inv;
        o.w = acc[i][3] * inv;
        *(float4*)&O[((size_t)b * L_ + q0 + ty * 4 + i) * E_ + h * D_ + tx * 4] = o;
    }
}

// =================================================================================
// kernel_launch
// inputs: 0 query, 1 key, 2 value, 3 Wq, 4 bq, 5 Wk, 6 bk, 7 Wv, 8 bv, 9 Wo, 10 bo
// =================================================================================
extern "C" void kernel_launch(void* const* d_in, const int* in_sizes, int n_in,
                              void* d_out, int out_size)
{
    (void)in_sizes; (void)n_in; (void)out_size;

    const float* query = (const float*)d_in[0];
    const float* key   = (const float*)d_in[1];
    const float* value = (const float*)d_in[2];
    const float* Wq    = (const float*)d_in[3];
    const float* bq    = (const float*)d_in[4];
    const float* Wk    = (const float*)d_in[5];
    const float* bk    = (const float*)d_in[6];
    const float* Wv    = (const float*)d_in[7];
    const float* bv    = (const float*)d_in[8];
    const float* Wo    = (const float*)d_in[9];
    const float* bo    = (const float*)d_in[10];
    float* out = (float*)d_out;

    float *qp, *kp, *vp, *ap;
    cudaGetSymbolAddress((void**)&qp, g_q);
    cudaGetSymbolAddress((void**)&kp, g_k);
    cudaGetSymbolAddress((void**)&vp, g_v);
    cudaGetSymbolAddress((void**)&ap, g_attn);

    dim3 gthreads(256);
    dim3 ggrid(E_ / GT_N, MTOT / GT_M);   // (8, 64)

    // Q/K/V projections
    gemm_nt_bias<<<ggrid, gthreads>>>(query, Wq, bq, qp, MTOT, E_, E_);
    gemm_nt_bias<<<ggrid, gthreads>>>(key,   Wk, bk, kp, MTOT, E_, E_);
    gemm_nt_bias<<<ggrid, gthreads>>>(value, Wv, bv, vp, MTOT, E_, E_);

    // attention
    const int fa_smem = 4 * 64 * FA_LDS * (int)sizeof(float);  // 66560 B
    cudaFuncSetAttribute(flash_attn, cudaFuncAttributeMaxDynamicSharedMemorySize, fa_smem);
    dim3 agrid(L_ / FA_BM, B_ * H_);      // (32, 64)
    flash_attn<<<agrid, 256, fa_smem>>>(qp, kp, vp, ap);

    // output projection -> d_out
    gemm_nt_bias<<<ggrid, gthreads>>>(ap, Wo, bo, out, MTOT, E_, E_);
}

// round 10
// speedup vs baseline: 1.0005x; 1.0005x over previous
#include <cuda_runtime.h>
#include <math.h>

#define B_    4
#define L_    2048
#define E_    1024
#define H_    16
#define D_    64
#define MTOT  (B_ * L_)   // 8192

// ---------------- scratch (device globals: no allocations allowed) ----------------
__device__ float g_q[MTOT * E_];
__device__ float g_k[MTOT * E_];
__device__ float g_v[MTOT * E_];
__device__ float g_attn[MTOT * E_];

// =================================================================================
// Projection GEMM:  Y[M,N] = X[M,K] @ W[N,K]^T + bias[N]
// Both operands are K-contiguous (NT GEMM). 128x128 tile, BK=16, 256 threads,
// 8x8 micro-tile per thread, smem staged transposed ([k][m]) for float4 reads.
// =================================================================================
#define GT_M   128
#define GT_N   128
#define GT_K   16
#define GT_PAD 4     // pad 4 keeps 16B alignment for float4 reads, 2-way store conflict max

__global__ __launch_bounds__(256, 2)
void gemm_nt_bias(const float* __restrict__ X, const float* __restrict__ W,
                  const float* __restrict__ bias, float* __restrict__ Y,
                  int M, int N, int K)
{
    __shared__ float Xs[GT_K][GT_M + GT_PAD];
    __shared__ float Ws[GT_K][GT_N + GT_PAD];

    const int tid  = threadIdx.x;
    const int tx   = tid & 15;
    const int ty   = tid >> 4;
    const int m0   = blockIdx.y * GT_M;
    const int n0   = blockIdx.x * GT_N;
    const int lrow = tid >> 2;        // 0..63
    const int lk   = (tid & 3) << 2;  // 0,4,8,12

    float acc[8][8];
    #pragma unroll
    for (int i = 0; i < 8; i++)
        #pragma unroll
        for (int j = 0; j < 8; j++) acc[i][j] = 0.0f;

    for (int k0 = 0; k0 < K; k0 += GT_K) {
        #pragma unroll
        for (int half = 0; half < 2; half++) {
            int r = lrow + half * 64;
            float4 xv = *(const float4*)&X[(size_t)(m0 + r) * K + k0 + lk];
            Xs[lk + 0][r] = xv.x; Xs[lk + 1][r] = xv.y;
            Xs[lk + 2][r] = xv.z; Xs[lk + 3][r] = xv.w;
            float4 wv = *(const float4*)&W[(size_t)(n0 + r) * K + k0 + lk];
            Ws[lk + 0][r] = wv.x; Ws[lk + 1][r] = wv.y;
            Ws[lk + 2][r] = wv.z; Ws[lk + 3][r] = wv.w;
        }
        __syncthreads();

        #pragma unroll
        for (int kk = 0; kk < GT_K; kk++) {
            float a[8], b[8];
            *(float4*)&a[0] = *(const float4*)&Xs[kk][ty * 4];
            *(float4*)&a[4] = *(const float4*)&Xs[kk][64 + ty * 4];
            *(float4*)&b[0] = *(const float4*)&Ws[kk][tx * 4];
            *(float4*)&b[4] = *(const float4*)&Ws[kk][64 + tx * 4];
            #pragma unroll
            for (int i = 0; i < 8; i++)
                #pragma unroll
                for (int j = 0; j < 8; j++)
                    acc[i][j] = fmaf(a[i], b[j], acc[i][j]);
        }
        __syncthreads();
    }

    // epilogue: add bias, float4 stores
    #pragma unroll
    for (int i = 0; i < 8; i++) {
        int m = m0 + ((i < 4) ? (ty * 4 + i) : (64 + ty * 4 + (i - 4)));
        #pragma unroll
        for (int jh = 0; jh < 2; jh++) {
            int n = n0 + jh * 64 + tx * 4;
            float4 o;
            o.x = acc[i][jh * 4 + 0] + bias[n + 0];
            o.y = acc[i][jh * 4 + 1] + bias[n + 1];
            o.z = acc[i][jh * 4 + 2] + bias[n + 2];
            o.w = acc[i][jh * 4 + 3] + bias[n + 3];
            *(float4*)&Y[(size_t)m * N + n] = o;
        }
    }
}

// =================================================================================
// Flash attention (fp32, online softmax). One block per (b,h, 64-row q tile).
// 256 threads as 16x16; each thread owns a 4x4 micro-tile of S (64x64) and of
// O (64 rows x 64 dims). Row-group = 16 lanes sharing ty -> shfl_xor reductions.
// Smem rows padded to 65 floats: compute-phase scalar reads are conflict-free.
// =================================================================================
#define FA_BM  64
#define FA_BN  64
#define FA_LDS 65

__global__ __launch_bounds__(256, 2)
void flash_attn(const float* __restrict__ Q, const float* __restrict__ K,
                const float* __restrict__ V, float* __restrict__ O)
{
    extern __shared__ float sm[];
    float* Qs = sm;                   // [64][65]
    float* Ks = Qs + 64 * FA_LDS;     // [64][65]
    float* Vs = Ks + 64 * FA_LDS;     // [64][65]
    float* Ps = Vs + 64 * FA_LDS;     // [64][65]

    const int tid = threadIdx.x;
    const int tx  = tid & 15;
    const int ty  = tid >> 4;
    const int bh  = blockIdx.y;
    const int b   = bh >> 4;          // / H_
    const int h   = bh & 15;          // % H_
    const int q0  = blockIdx.x * FA_BM;

    const float* qg = Q + ((size_t)b * L_ + q0) * E_ + h * D_;
    const float* kg = K + ((size_t)b * L_) * E_ + h * D_;
    const float* vg = V + ((size_t)b * L_) * E_ + h * D_;

    const float scale = 0.03125f;     // 1/sqrt(1024)

    // load + scale Q tile (64 rows x 64 dims)
    #pragma unroll
    for (int p = 0; p < 4; p++) {
        int idx = p * 256 + tid;
        int r   = idx >> 4;
        int dc  = (idx & 15) << 2;
        float4 v = *(const float4*)&qg[(size_t)r * E_ + dc];
        Qs[r * FA_LDS + dc + 0] = v.x * scale;
        Qs[r * FA_LDS + dc + 1] = v.y * scale;
        Qs[r * FA_LDS + dc + 2] = v.z * scale;
        Qs[r * FA_LDS + dc + 3] = v.w * scale;
    }

    float m_i[4], l_i[4], acc[4][4];
    #pragma unroll
    for (int i = 0; i < 4; i++) {
        m_i[i] = -INFINITY;
        l_i[i] = 0.0f;
        #pragma unroll
        for (int j = 0; j < 4; j++) acc[i][j] = 0.0f;
    }

    for (int n0 = 0; n0 < L_; n0 += FA_BN) {
        __syncthreads();   // prev tile fully consumed (and Q visible on first iter)

        // load K, V tiles (natural layout, padded rows)
        #pragma unroll
        for (int p = 0; p < 4; p++) {
            int idx = p * 256 + tid;
            int r   = idx >> 4;
            int dc  = (idx & 15) << 2;
            float4 kv = *(const float4*)&kg[(size_t)(n0 + r) * E_ + dc];
            Ks[r * FA_LDS + dc + 0] = kv.x;
            Ks[r * FA_LDS + dc + 1] = kv.y;
            Ks[r * FA_LDS + dc + 2] = kv.z;
            Ks[r * FA_LDS + dc + 3] = kv.w;
            float4 vv = *(const float4*)&vg[(size_t)(n0 + r) * E_ + dc];
            Vs[r * FA_LDS + dc + 0] = vv.x;
            Vs[r * FA_LDS + dc + 1] = vv.y;
            Vs[r * FA_LDS + dc + 2] = vv.z;
            Vs[r * FA_LDS + dc + 3] = vv.w;
        }
        __syncthreads();

        // ---- GEMM1: s[4][4] = (Q tile) @ (K tile)^T, inner product along d ----
        float s[4][4];
        #pragma unroll
        for (int i = 0; i < 4; i++)
            #pragma unroll
            for (int j = 0; j < 4; j++) s[i][j] = 0.0f;

        #pragma unroll 8
        for (int kk = 0; kk < D_; kk++) {
            float a[4], bb[4];
            #pragma unroll
            for (int i = 0; i < 4; i++) a[i]  = Qs[(ty * 4 + i) * FA_LDS + kk];
            #pragma unroll
            for (int j = 0; j < 4; j++) bb[j] = Ks[(tx * 4 + j) * FA_LDS + kk];
            #pragma unroll
            for (int i = 0; i < 4; i++)
                #pragma unroll
                for (int j = 0; j < 4; j++)
                    s[i][j] = fmaf(a[i], bb[j], s[i][j]);
        }

        // ---- online softmax (row group = 16 lanes, shfl_xor over tx bits) ----
        #pragma unroll
        for (int i = 0; i < 4; i++) {
            float rmax = fmaxf(fmaxf(s[i][0], s[i][1]), fmaxf(s[i][2], s[i][3]));
            rmax = fmaxf(rmax, __shfl_xor_sync(0xffffffffu, rmax, 1));
            rmax = fmaxf(rmax, __shfl_xor_sync(0xffffffffu, rmax, 2));
            rmax = fmaxf(rmax, __shfl_xor_sync(0xffffffffu, rmax, 4));
            rmax = fmaxf(rmax, __shfl_xor_sync(0xffffffffu, rmax, 8));
            float mnew = fmaxf(m_i[i], rmax);

            float p0 = __expf(s[i][0] - mnew);
            float p1 = __expf(s[i][1] - mnew);
            float p2 = __expf(s[i][2] - mnew);
            float p3 = __expf(s[i][3] - mnew);
            float rsum = (p0 + p1) + (p2 + p3);
            rsum += __shfl_xor_sync(0xffffffffu, rsum, 1);
            rsum += __shfl_xor_sync(0xffffffffu, rsum, 2);
            rsum += __shfl_xor_sync(0xffffffffu, rsum, 4);
            rsum += __shfl_xor_sync(0xffffffffu, rsum, 8);

            float alpha = __expf(m_i[i] - mnew);   // 0 when m_i = -inf
            l_i[i] = l_i[i] * alpha + rsum;
            m_i[i] = mnew;
            #pragma unroll
            for (int j = 0; j < 4; j++) acc[i][j] *= alpha;

            int prow = (ty * 4 + i) * FA_LDS + tx * 4;
            Ps[prow + 0] = p0; Ps[prow + 1] = p1;
            Ps[prow + 2] = p2; Ps[prow + 3] = p3;
        }
        __syncthreads();

        // ---- GEMM2: acc += P @ V ----
        #pragma unroll 8
        for (int nn = 0; nn < FA_BN; nn++) {
            float a[4], bb[4];
            #pragma unroll
            for (int i = 0; i < 4; i++) a[i]  = Ps[(ty * 4 + i) * FA_LDS + nn];
            #pragma unroll
            for (int j = 0; j < 4; j++) bb[j] = Vs[nn * FA_LDS + tx * 4 + j];
            #pragma unroll
            for (int i = 0; i < 4; i++)
                #pragma unroll
                for (int j = 0; j < 4; j++)
                    acc[i][j] = fmaf(a[i], bb[j], acc[i][j]);
        }
    }

    // epilogue: normalize, write [b, q, h, d]
    #pragma unroll
    for (int i = 0; i < 4; i++) {
        float inv = 1.0f / l_i[i];
        float4 o;
        o.x = acc[i][0] * inv;
        o.y = acc[i][1] * inv;
        o.z = acc[i][2] * inv;
        o.w = acc[i][3] * inv;
        *(float4*)&O[((size_t)b * L_ + q0 + ty * 4 + i) * E_ + h * D_ + tx * 4] = o;
    }
}

// =================================================================================
// kernel_launch
// inputs: 0 query, 1 key, 2 value, 3 Wq, 4 bq, 5 Wk, 6 bk, 7 Wv, 8 bv, 9 Wo, 10 bo
// =================================================================================
extern "C" void kernel_launch(void* const* d_in, const int* in_sizes, int n_in,
                              void* d_out, int out_size)
{
    (void)in_sizes; (void)n_in; (void)out_size;

    const float* query = (const float*)d_in[0];
    const float* key   = (const float*)d_in[1];
    const float* value = (const float*)d_in[2];
    const float* Wq    = (const float*)d_in[3];
    const float* bq    = (const float*)d_in[4];
    const float* Wk    = (const float*)d_in[5];
    const float* bk    = (const float*)d_in[6];
    const float* Wv    = (const float*)d_in[7];
    const float* bv    = (const float*)d_in[8];
    const float* Wo    = (const float*)d_in[9];
    const float* bo    = (const float*)d_in[10];
    float* out = (float*)d_out;

    float *qp, *kp, *vp, *ap;
    cudaGetSymbolAddress((void**)&qp, g_q);
    cudaGetSymbolAddress((void**)&kp, g_k);
    cudaGetSymbolAddress((void**)&vp, g_v);
    cudaGetSymbolAddress((void**)&ap, g_attn);

    dim3 gthreads(256);
    dim3 ggrid(E_ / GT_N, MTOT / GT_M);   // (8, 64)

    // Q/K/V projections
    gemm_nt_bias<<<ggrid, gthreads>>>(query, Wq, bq, qp, MTOT, E_, E_);
    gemm_nt_bias<<<ggrid, gthreads>>>(key,   Wk, bk, kp, MTOT, E_, E_);
    gemm_nt_bias<<<ggrid, gthreads>>>(value, Wv, bv, vp, MTOT, E_, E_);

    // attention
    const int fa_smem = 4 * 64 * FA_LDS * (int)sizeof(float);  // 66560 B
    cudaFuncSetAttribute(flash_attn, cudaFuncAttributeMaxDynamicSharedMemorySize, fa_smem);
    dim3 agrid(L_ / FA_BM, B_ * H_);      // (32, 64)
    flash_attn<<<agrid, 256, fa_smem>>>(qp, kp, vp, ap);

    // output projection -> d_out
    gemm_nt_bias<<<ggrid, gthreads>>>(ap, Wo, bo, out, MTOT, E_, E_);
}

// round 11
// speedup vs baseline: 1.0006x; 1.0001x over previous
#include <cuda_runtime.h>
#include <math.h>

#define B_    4
#define L_    2048
#define E_    1024
#define H_    16
#define D_    64
#define MTOT  (B_ * L_)   // 8192

// ---------------- scratch (device globals: no allocations allowed) ----------------
__device__ float g_q[MTOT * E_];
__device__ float g_k[MTOT * E_];
__device__ float g_v[MTOT * E_];
__device__ float g_attn[MTOT * E_];

// =================================================================================
// Projection GEMM:  Y[M,N] = X[M,K] @ W[N,K]^T + bias[N]
// Both operands are K-contiguous (NT GEMM). 128x128 tile, BK=16, 256 threads,
// 8x8 micro-tile per thread, smem staged transposed ([k][m]) for float4 reads.
// =================================================================================
#define GT_M   128
#define GT_N   128
#define GT_K   16
#define GT_PAD 4     // pad 4 keeps 16B alignment for float4 reads, 2-way store conflict max

__global__ __launch_bounds__(256, 2)
void gemm_nt_bias(const float* __restrict__ X, const float* __restrict__ W,
                  const float* __restrict__ bias, float* __restrict__ Y,
                  int M, int N, int K)
{
    __shared__ float Xs[GT_K][GT_M + GT_PAD];
    __shared__ float Ws[GT_K][GT_N + GT_PAD];

    const int tid  = threadIdx.x;
    const int tx   = tid & 15;
    const int ty   = tid >> 4;
    const int m0   = blockIdx.y * GT_M;
    const int n0   = blockIdx.x * GT_N;
    const int lrow = tid >> 2;        // 0..63
    const int lk   = (tid & 3) << 2;  // 0,4,8,12

    float acc[8][8];
    #pragma unroll
    for (int i = 0; i < 8; i++)
        #pragma unroll
        for (int j = 0; j < 8; j++) acc[i][j] = 0.0f;

    for (int k0 = 0; k0 < K; k0 += GT_K) {
        #pragma unroll
        for (int half = 0; half < 2; half++) {
            int r = lrow + half * 64;
            float4 xv = *(const float4*)&X[(size_t)(m0 + r) * K + k0 + lk];
            Xs[lk + 0][r] = xv.x; Xs[lk + 1][r] = xv.y;
            Xs[lk + 2][r] = xv.z; Xs[lk + 3][r] = xv.w;
            float4 wv = *(const float4*)&W[(size_t)(n0 + r) * K + k0 + lk];
            Ws[lk + 0][r] = wv.x; Ws[lk + 1][r] = wv.y;
            Ws[lk + 2][r] = wv.z; Ws[lk + 3][r] = wv.w;
        }
        __syncthreads();

        #pragma unroll
        for (int kk = 0; kk < GT_K; kk++) {
            float a[8], b[8];
            *(float4*)&a[0] = *(const float4*)&Xs[kk][ty * 4];
            *(float4*)&a[4] = *(const float4*)&Xs[kk][64 + ty * 4];
            *(float4*)&b[0] = *(const float4*)&Ws[kk][tx * 4];
            *(float4*)&b[4] = *(const float4*)&Ws[kk][64 + tx * 4];
            #pragma unroll
            for (int i = 0; i < 8; i++)
                #pragma unroll
                for (int j = 0; j < 8; j++)
                    acc[i][j] = fmaf(a[i], b[j], acc[i][j]);
        }
        __syncthreads();
    }

    // epilogue: add bias, float4 stores
    #pragma unroll
    for (int i = 0; i < 8; i++) {
        int m = m0 + ((i < 4) ? (ty * 4 + i) : (64 + ty * 4 + (i - 4)));
        #pragma unroll
        for (int jh = 0; jh < 2; jh++) {
            int n = n0 + jh * 64 + tx * 4;
            float4 o;
            o.x = acc[i][jh * 4 + 0] + bias[n + 0];
            o.y = acc[i][jh * 4 + 1] + bias[n + 1];
            o.z = acc[i][jh * 4 + 2] + bias[n + 2];
            o.w = acc[i][jh * 4 + 3] + bias[n + 3];
            *(float4*)&Y[(size_t)m * N + n] = o;
        }
    }
}

// =================================================================================
// Flash attention (fp32, online softmax). One block per (b,h, 64-row q tile).
// 256 threads as 16x16; each thread owns a 4x4 micro-tile of S (64x64) and of
// O (64 rows x 64 dims). Row-group = 16 lanes sharing ty -> shfl_xor reductions.
// Smem rows padded to 65 floats: compute-phase scalar reads are conflict-free.
// =================================================================================
#define FA_BM  64
#define FA_BN  64
#define FA_LDS 65

__global__ __launch_bounds__(256, 2)
void flash_attn(const float* __restrict__ Q, const float* __restrict__ K,
                const float* __restrict__ V, float* __restrict__ O)
{
    extern __shared__ float sm[];
    float* Qs = sm;                   // [64][65]
    float* Ks = Qs + 64 * FA_LDS;     // [64][65]
    float* Vs = Ks + 64 * FA_LDS;     // [64][65]
    float* Ps = Vs + 64 * FA_LDS;     // [64][65]

    const int tid = threadIdx.x;
    const int tx  = tid & 15;
    const int ty  = tid >> 4;
    const int bh  = blockIdx.y;
    const int b   = bh >> 4;          // / H_
    const int h   = bh & 15;          // % H_
    const int q0  = blockIdx.x * FA_BM;

    const float* qg = Q + ((size_t)b * L_ + q0) * E_ + h * D_;
    const float* kg = K + ((size_t)b * L_) * E_ + h * D_;
    const float* vg = V + ((size_t)b * L_) * E_ + h * D_;

    const float scale = 0.03125f;     // 1/sqrt(1024)

    // load + scale Q tile (64 rows x 64 dims)
    #pragma unroll
    for (int p = 0; p < 4; p++) {
        int idx = p * 256 + tid;
        int r   = idx >> 4;
        int dc  = (idx & 15) << 2;
        float4 v = *(const float4*)&qg[(size_t)r * E_ + dc];
        Qs[r * FA_LDS + dc + 0] = v.x * scale;
        Qs[r * FA_LDS + dc + 1] = v.y * scale;
        Qs[r * FA_LDS + dc + 2] = v.z * scale;
        Qs[r * FA_LDS + dc + 3] = v.w * scale;
    }

    float m_i[4], l_i[4], acc[4][4];
    #pragma unroll
    for (int i = 0; i < 4; i++) {
        m_i[i] = -INFINITY;
        l_i[i] = 0.0f;
        #pragma unroll
        for (int j = 0; j < 4; j++) acc[i][j] = 0.0f;
    }

    for (int n0 = 0; n0 < L_; n0 += FA_BN) {
        __syncthreads();   // prev tile fully consumed (and Q visible on first iter)

        // load K, V tiles (natural layout, padded rows)
        #pragma unroll
        for (int p = 0; p < 4; p++) {
            int idx = p * 256 + tid;
            int r   = idx >> 4;
            int dc  = (idx & 15) << 2;
            float4 kv = *(const float4*)&kg[(size_t)(n0 + r) * E_ + dc];
            Ks[r * FA_LDS + dc + 0] = kv.x;
            Ks[r * FA_LDS + dc + 1] = kv.y;
            Ks[r * FA_LDS + dc + 2] = kv.z;
            Ks[r * FA_LDS + dc + 3] = kv.w;
            float4 vv = *(const float4*)&vg[(size_t)(n0 + r) * E_ + dc];
            Vs[r * FA_LDS + dc + 0] = vv.x;
            Vs[r * FA_LDS + dc + 1] = vv.y;
            Vs[r * FA_LDS + dc + 2] = vv.z;
            Vs[r * FA_LDS + dc + 3] = vv.w;
        }
        __syncthreads();

        // ---- GEMM1: s[4][4] = (Q tile) @ (K tile)^T, inner product along d ----
        float s[4][4];
        #pragma unroll
        for (int i = 0; i < 4; i++)
            #pragma unroll
            for (int j = 0; j < 4; j++) s[i][j] = 0.0f;

        #pragma unroll 8
        for (int kk = 0; kk < D_; kk++) {
            float a[4], bb[4];
            #pragma unroll
            for (int i = 0; i < 4; i++) a[i]  = Qs[(ty * 4 + i) * FA_LDS + kk];
            #pragma unroll
            for (int j = 0; j < 4; j++) bb[j] = Ks[(tx * 4 + j) * FA_LDS + kk];
            #pragma unroll
            for (int i = 0; i < 4; i++)
                #pragma unroll
                for (int j = 0; j < 4; j++)
                    s[i][j] = fmaf(a[i], bb[j], s[i][j]);
        }

        // ---- online softmax (row group = 16 lanes, shfl_xor over tx bits) ----
        #pragma unroll
        for (int i = 0; i < 4; i++) {
            float rmax = fmaxf(fmaxf(s[i][0], s[i][1]), fmaxf(s[i][2], s[i][3]));
            rmax = fmaxf(rmax, __shfl_xor_sync(0xffffffffu, rmax, 1));
            rmax = fmaxf(rmax, __shfl_xor_sync(0xffffffffu, rmax, 2));
            rmax = fmaxf(rmax, __shfl_xor_sync(0xffffffffu, rmax, 4));
            rmax = fmaxf(rmax, __shfl_xor_sync(0xffffffffu, rmax, 8));
            float mnew = fmaxf(m_i[i], rmax);

            float p0 = __expf(s[i][0] - mnew);
            float p1 = __expf(s[i][1] - mnew);
            float p2 = __expf(s[i][2] - mnew);
            float p3 = __expf(s[i][3] - mnew);
            float rsum = (p0 + p1) + (p2 + p3);
            rsum += __shfl_xor_sync(0xffffffffu, rsum, 1);
            rsum += __shfl_xor_sync(0xffffffffu, rsum, 2);
            rsum += __shfl_xor_sync(0xffffffffu, rsum, 4);
            rsum += __shfl_xor_sync(0xffffffffu, rsum, 8);

            float alpha = __expf(m_i[i] - mnew);   // 0 when m_i = -inf
            l_i[i] = l_i[i] * alpha + rsum;
            m_i[i] = mnew;
            #pragma unroll
            for (int j = 0; j < 4; j++) acc[i][j] *= alpha;

            int prow = (ty * 4 + i) * FA_LDS + tx * 4;
            Ps[prow + 0] = p0; Ps[prow + 1] = p1;
            Ps[prow + 2] = p2; Ps[prow + 3] = p3;
        }
        __syncthreads();

        // ---- GEMM2: acc += P @ V ----
        #pragma unroll 8
        for (int nn = 0; nn < FA_BN; nn++) {
            float a[4], bb[4];
            #pragma unroll
            for (int i = 0; i < 4; i++) a[i]  = Ps[(ty * 4 + i) * FA_LDS + nn];
            #pragma unroll
            for (int j = 0; j < 4; j++) bb[j] = Vs[nn * FA_LDS + tx * 4 + j];
            #pragma unroll
            for (int i = 0; i < 4; i++)
                #pragma unroll
                for (int j = 0; j < 4; j++)
                    acc[i][j] = fmaf(a[i], bb[j], acc[i][j]);
        }
    }

    // epilogue: normalize, write [b, q, h, d]
    #pragma unroll
    for (int i = 0; i < 4; i++) {
        float inv = 1.0f / l_i[i];
        float4 o;
        o.x = acc[i][0] * inv;
        o.y = acc[i][1] * inv;
        o.z = acc[i][2] * inv;
        o.w = acc[i][3] * inv;
        *(float4*)&O[((size_t)b * L_ + q0 + ty * 4 + i) * E_ + h * D_ + tx * 4] = o;
    }
}

// =================================================================================
// kernel_launch
// inputs: 0 query, 1 key, 2 value, 3 Wq, 4 bq, 5 Wk, 6 bk, 7 Wv, 8 bv, 9 Wo, 10 bo
// =================================================================================
extern "C" void kernel_launch(void* const* d_in, const int* in_sizes, int n_in,
                              void* d_out, int out_size)
{
    (void)in_sizes; (void)n_in; (void)out_size;

    const float* query = (const float*)d_in[0];
    const float* key   = (const float*)d_in[1];
    const float* value = (const float*)d_in[2];
    const float* Wq    = (const float*)d_in[3];
    const float* bq    = (const float*)d_in[4];
    const float* Wk    = (const float*)d_in[5];
    const float* bk    = (const float*)d_in[6];
    const float* Wv    = (const float*)d_in[7];
    const float* bv    = (const float*)d_in[8];
    const float* Wo    = (const float*)d_in[9];
    const float* bo    = (const float*)d_in[10];
    float* out = (float*)d_out;

    float *qp, *kp, *vp, *ap;
    cudaGetSymbolAddress((void**)&qp, g_q);
    cudaGetSymbolAddress((void**)&kp, g_k);
    cudaGetSymbolAddress((void**)&vp, g_v);
    cudaGetSymbolAddress((void**)&ap, g_attn);

    dim3 gthreads(256);
    dim3 ggrid(E_ / GT_N, MTOT / GT_M);   // (8, 64)

    // Q/K/V projections
    gemm_nt_bias<<<ggrid, gthreads>>>(query, Wq, bq, qp, MTOT, E_, E_);
    gemm_nt_bias<<<ggrid, gthreads>>>(key,   Wk, bk, kp, MTOT, E_, E_);
    gemm_nt_bias<<<ggrid, gthreads>>>(value, Wv, bv, vp, MTOT, E_, E_);

    // attention
    const int fa_smem = 4 * 64 * FA_LDS * (int)sizeof(float);  // 66560 B
    cudaFuncSetAttribute(flash_attn, cudaFuncAttributeMaxDynamicSharedMemorySize, fa_smem);
    dim3 agrid(L_ / FA_BM, B_ * H_);      // (32, 64)
    flash_attn<<<agrid, 256, fa_smem>>>(qp, kp, vp, ap);

    // output projection -> d_out
    gemm_nt_bias<<<ggrid, gthreads>>>(ap, Wo, bo, out, MTOT, E_, E_);
}